// round 14
// baseline (speedup 1.0000x reference)
#include <cuda_runtime.h>
#include <cuda_fp16.h>
#include <cstdint>
#include <math.h>

#define SEQ 8192
#define EMB 2048
#define HID 2048
#define WROW (EMB + HID)

// ---------------- persistent recurrent kernel config ----------------
#define G   128   // CTAs (<= 148 SMs, 1 CTA/SM -> all co-resident)
#define RPC 16    // rows per CTA (HID / G)
#define RT  512   // threads per CTA

// ---------------- device scratch ----------------
__device__ __align__(16) __half2 g_wh[3ull * HID * HID / 2];   // fp16 h-part weights [m][row][col]
__device__ __align__(16) __half2 g_wx[3ull * HID * EMB / 2];   // fp16 x-part weights [m][row][col]
__device__ __align__(16) __half2 g_Xh[(size_t)SEQ * EMB / 2];  // fp16 inputs
__device__ float    g_P [3ull * SEQ * HID];   // precomputed x-projections + bias
__device__ __align__(16) __half2 g_h [HID / 2];   // hidden state exchange (fp16)
__device__ __align__(16) __half2 g_rh[HID / 2];   // r*h exchange (fp16)
__device__ unsigned g_count;

// ---------------- init (reset per launch / per graph replay) ----------------
__global__ void init_kernel() {
  int i = blockIdx.x * blockDim.x + threadIdx.x;
  if (i < HID / 2) ((unsigned*)g_h)[i] = 0u;
  if (i == 0) g_count = 0u;
}

// ---------------- fp32 -> fp16 conversions ----------------
__global__ void convert_X_kernel(const float* __restrict__ X) {
  size_t i4 = (size_t)blockIdx.x * blockDim.x + threadIdx.x;
  if (i4 >= (size_t)SEQ * EMB / 4) return;
  float4 v = ((const float4*)X)[i4];
  g_Xh[i4 * 2 + 0] = __floats2half2_rn(v.x, v.y);
  g_Xh[i4 * 2 + 1] = __floats2half2_rn(v.z, v.w);
}

__global__ void convert_W_kernel(const float* __restrict__ Wz,
                                 const float* __restrict__ Wr,
                                 const float* __restrict__ Wh) {
  size_t i4 = (size_t)blockIdx.x * blockDim.x + threadIdx.x;
  const size_t total4 = 3ull * HID * WROW / 4;
  if (i4 >= total4) return;
  size_t idx = i4 * 4;
  int m = (int)(idx / ((size_t)HID * WROW));
  size_t rem = idx - (size_t)m * HID * WROW;
  int r = (int)(rem / WROW);
  int c = (int)(rem - (size_t)r * WROW);
  const float* W = (m == 0) ? Wz : ((m == 1) ? Wr : Wh);
  float4 v = ((const float4*)(W + (size_t)r * WROW + c))[0];
  __half2 h01 = __floats2half2_rn(v.x, v.y);
  __half2 h23 = __floats2half2_rn(v.z, v.w);
  if (c < EMB) {
    size_t o = ((size_t)(m * HID + r) * EMB + c) / 2;
    g_wx[o] = h01;
    g_wx[o + 1] = h23;
  } else {
    size_t o = ((size_t)(m * HID + r) * HID + (c - EMB)) / 2;
    g_wh[o] = h01;
    g_wh[o + 1] = h23;
  }
}

// ---------------- tensor-core x-projection GEMM ----------------
__device__ __forceinline__ uint32_t smem_u32(const void* p) {
  return (uint32_t)__cvta_generic_to_shared(p);
}

__device__ __forceinline__ void ldsm4(uint32_t* r, uint32_t addr) {
  asm volatile("ldmatrix.sync.aligned.m8n8.x4.shared.b16 {%0,%1,%2,%3}, [%4];"
    : "=r"(r[0]), "=r"(r[1]), "=r"(r[2]), "=r"(r[3]) : "r"(addr));
}

__device__ __forceinline__ void mma16816(float* d, const uint32_t* a, const uint32_t* b) {
  asm volatile(
    "mma.sync.aligned.m16n8k16.row.col.f32.f16.f16.f32 "
    "{%0,%1,%2,%3}, {%4,%5,%6,%7}, {%8,%9}, {%0,%1,%2,%3};"
    : "+f"(d[0]), "+f"(d[1]), "+f"(d[2]), "+f"(d[3])
    : "r"(a[0]), "r"(a[1]), "r"(a[2]), "r"(a[3]), "r"(b[0]), "r"(b[1]));
}

__global__ __launch_bounds__(256) void xproj_mma_kernel(
    const float* __restrict__ bz, const float* __restrict__ br, const float* __restrict__ bh) {
  __shared__ __half As[128][40];
  __shared__ __half Bs[128][40];

  int m  = blockIdx.z;
  int bM = blockIdx.y * 128;
  int bN = blockIdx.x * 128;
  const __half* Asrc = (const __half*)g_Xh;
  const __half* Bsrc = (const __half*)g_wx + (size_t)m * HID * EMB;
  const float* bias = (m == 0) ? bz : ((m == 1) ? br : bh);

  int tid = threadIdx.x;
  int lane = tid & 31;
  int wid = tid >> 5;
  int wm = wid >> 1;
  int wn = wid & 1;

  float d[2][8][4];
#pragma unroll
  for (int mf = 0; mf < 2; mf++)
#pragma unroll
    for (int nf = 0; nf < 8; nf++)
#pragma unroll
      for (int q = 0; q < 4; q++) d[mf][nf][q] = 0.0f;

  for (int kt = 0; kt < EMB; kt += 32) {
#pragma unroll
    for (int i = 0; i < 2; i++) {
      int f = tid + i * 256;
      int row = f >> 2;
      int q = f & 3;
      *(uint4*)&As[row][q * 8] = *(const uint4*)&Asrc[(size_t)(bM + row) * EMB + kt + q * 8];
      *(uint4*)&Bs[row][q * 8] = *(const uint4*)&Bsrc[(size_t)(bN + row) * EMB + kt + q * 8];
    }
    __syncthreads();

#pragma unroll
    for (int ks = 0; ks < 32; ks += 16) {
      uint32_t a[2][4];
#pragma unroll
      for (int mf = 0; mf < 2; mf++) {
        int r = wm * 32 + mf * 16 + (lane & 15);
        int c = ks + ((lane >> 4) << 3);
        ldsm4(a[mf], smem_u32(&As[r][c]));
      }
      uint32_t b[8][2];
#pragma unroll
      for (int nf2 = 0; nf2 < 4; nf2++) {
        int t4 = lane >> 3;
        int r = wn * 64 + nf2 * 16 + ((t4 >> 1) << 3) + (lane & 7);
        int c = ks + ((t4 & 1) << 3);
        uint32_t rr[4];
        ldsm4(rr, smem_u32(&Bs[r][c]));
        b[nf2 * 2][0]     = rr[0];
        b[nf2 * 2][1]     = rr[1];
        b[nf2 * 2 + 1][0] = rr[2];
        b[nf2 * 2 + 1][1] = rr[3];
      }
#pragma unroll
      for (int mf = 0; mf < 2; mf++)
#pragma unroll
        for (int nf = 0; nf < 8; nf++) mma16816(d[mf][nf], a[mf], b[nf]);
    }
    __syncthreads();
  }

  int rowg = lane >> 2;
  int colg = (lane & 3) * 2;
#pragma unroll
  for (int mf = 0; mf < 2; mf++) {
#pragma unroll
    for (int nf = 0; nf < 8; nf++) {
      int t0 = bM + wm * 32 + mf * 16 + rowg;
      int c0 = bN + wn * 64 + nf * 8 + colg;
      float b0 = bias[c0];
      float b1 = bias[c0 + 1];
      float2 v0;
      v0.x = d[mf][nf][0] + b0;
      v0.y = d[mf][nf][1] + b1;
      float2 v1;
      v1.x = d[mf][nf][2] + b0;
      v1.y = d[mf][nf][3] + b1;
      *(float2*)&g_P[((size_t)m * SEQ + t0    ) * HID + c0] = v0;
      *(float2*)&g_P[((size_t)m * SEQ + t0 + 8) * HID + c0] = v1;
    }
  }
}

// ---------------- grid barrier (R7 verbatim: red.release + nanosleep poll) ----------------
__device__ __forceinline__ void grid_barrier(unsigned target) {
  __syncthreads();
  if (threadIdx.x == 0) {
    unsigned* cnt = &g_count;
    asm volatile("red.release.gpu.global.add.u32 [%0], %1;" :: "l"(cnt), "r"(1u) : "memory");
    unsigned v;
    asm volatile("ld.acquire.gpu.u32 %0, [%1];" : "=r"(v) : "l"(cnt) : "memory");
    while (v < target) {
      __nanosleep(32);
      asm volatile("ld.acquire.gpu.u32 %0, [%1];" : "=r"(v) : "l"(cnt) : "memory");
    }
  }
  __syncthreads();
}

// L1-bypass 8B load (g_h/g_rh mutate cross-SM every step)
__device__ __forceinline__ uint2 ldcv2(const uint2* p) {
  uint2 v;
  asm volatile("ld.global.cv.v2.u32 {%0,%1}, [%2];" : "=r"(v.x), "=r"(v.y) : "l"(p));
  return v;
}

// fp16 dot of 16 half2 pairs, fp32-flushed every 4 HFMA2 (chunk err ~2.5e-5 RMS)
__device__ __forceinline__ float dot16h(const __half2* w, const __half2* hh) {
  float s = 0.0f;
#pragma unroll
  for (int c = 0; c < 4; c++) {
    __half2 a = __hmul2(w[c * 4], hh[c * 4]);
#pragma unroll
    for (int k = 1; k < 4; k++) a = __hfma2(w[c * 4 + k], hh[c * 4 + k], a);
    float2 f = __half22float2(a);
    s += f.x + f.y;
  }
  return s;
}

// ---------------- persistent GRU recurrence ----------------
// SMEM: fp16 Wh [RPC][HID] (64KB) + half2 exchange vector (4KB).
#define GRU_SMEM (RPC * HID * 2 + HID * 2)

__global__ __launch_bounds__(RT, 1) void gru_kernel(float* __restrict__ out) {
  extern __shared__ char smem_raw[];
  __half2* sWh = (__half2*)smem_raw;                          // [RPC][1024] half2
  __half2* sh  = (__half2*)(smem_raw + RPC * HID * 2);        // [1024] half2 exchange
  __shared__ float sRed[2][32];
  __shared__ float sz[RPC];
  __shared__ float sHold[RPC];
  __shared__ float sHown[RPC];   // this CTA's rows of h, kept fp32 across steps
  __shared__ float sV[RPC];      // pair-packing staging for publishes

  const int b = blockIdx.x;
  const int tid = threadIdx.x;
  const int lane = tid & 31;
  const int w = tid >> 5;           // 16 warps
  const int chunk = w >> 3;         // vector half: 0 / 1
  const int pr = (w & 7) * 2;       // local row pair
  const int gbase = b * RPC;

  // Load Wh rows (m=2) into SMEM once.
  {
    const uint4* gsrc = (const uint4*)(g_wh + (2ull * HID * HID + (size_t)gbase * HID) / 2);
    uint4* sdst = (uint4*)smem_raw;
    for (int it = tid; it < RPC * HID / 8; it += RT) sdst[it] = gsrc[it];
  }
  if (tid < RPC) sHown[tid] = 0.0f;

  // Preload z,r weight rows into registers (contiguous per-thread layout: lane*16+j).
  __half2 rz0[16], rz1[16], rr0[16], rr1[16];
  {
    const __half2* z0 = g_wh + (size_t)(0 * HID + gbase + pr    ) * (HID / 2);
    const __half2* z1 = g_wh + (size_t)(0 * HID + gbase + pr + 1) * (HID / 2);
    const __half2* r0 = g_wh + (size_t)(1 * HID + gbase + pr    ) * (HID / 2);
    const __half2* r1 = g_wh + (size_t)(1 * HID + gbase + pr + 1) * (HID / 2);
    int base = (chunk << 9) + lane * 16;
#pragma unroll
    for (int j = 0; j < 16; j++) {
      rz0[j] = z0[base + j];
      rz1[j] = z1[base + j];
      rr0[j] = r0[base + j];
      rr1[j] = r1[base + j];
    }
  }
  __syncthreads();

  const __half2* shv = sh + (chunk << 9);
  const __half2* wh0 = sWh + (pr    ) * (HID / 2) + (chunk << 9);
  const __half2* wh1 = sWh + (pr + 1) * (HID / 2) + (chunk << 9);

  unsigned bt = 0;

  // Software-pipelined P prefetch (step t's values loaded during step t-1).
  float pzr_cur = 0.0f, ph_cur = 0.0f;
  if (tid < 32) {
    int row = tid & 15;
    int mm  = tid >> 4;
    pzr_cur = g_P[((size_t)mm * SEQ + 0) * HID + gbase + row];
  }
  if (tid < 16) ph_cur = g_P[((size_t)2 * SEQ + 0) * HID + gbase + tid];

  for (int t = 0; t < SEQ; t++) {
    int tn = (t + 1 < SEQ) ? (t + 1) : (SEQ - 1);
    float pzr_nxt = 0.0f, ph_nxt = 0.0f;
    if (tid < 32) {
      int row = tid & 15;
      int mm  = tid >> 4;
      pzr_nxt = g_P[((size_t)mm * SEQ + tn) * HID + gbase + row];
    }
    if (tid < 16) ph_nxt = g_P[((size_t)2 * SEQ + tn) * HID + gbase + tid];

    // ---- Phase A: stage h (half2, 4KB), compute z and r ----
    ((uint2*)sh)[tid] = ldcv2((const uint2*)g_h + tid);
    __syncthreads();

    // Per-thread h fragment (contiguous 16 half2 -> 4x LDS.128)
    uint4 hb[4];
    {
      const uint4* hp = (const uint4*)(shv + lane * 16);
#pragma unroll
      for (int q = 0; q < 4; q++) hb[q] = hp[q];
    }
    const __half2* hh = (const __half2*)hb;

    float az0 = dot16h(rz0, hh);
    float az1 = dot16h(rz1, hh);
    float ar0 = dot16h(rr0, hh);
    float ar1 = dot16h(rr1, hh);
#pragma unroll
    for (int o = 16; o; o >>= 1) {
      az0 += __shfl_xor_sync(0xffffffffu, az0, o);
      az1 += __shfl_xor_sync(0xffffffffu, az1, o);
      ar0 += __shfl_xor_sync(0xffffffffu, ar0, o);
      ar1 += __shfl_xor_sync(0xffffffffu, ar1, o);
    }
    if (lane == 0) {
      sRed[chunk][pr]          = az0;
      sRed[chunk][pr + 1]      = az1;
      sRed[chunk][16 + pr]     = ar0;
      sRed[chunk][16 + pr + 1] = ar1;
    }
    __syncthreads();

    if (tid < 32) {
      int row = tid & 15;
      float val = sRed[0][tid] + sRed[1][tid] + pzr_cur;
      float sg = 1.0f / (1.0f + __expf(-val));
      if (tid < 16) {
        sz[row]    = sg;             // z gate
        sHold[row] = sHown[row];     // old h (fp32 state)
      } else {
        sV[row] = sg * sHown[row];   // r*h (fp32), staged for packing
      }
    }
    __syncthreads();
    if (tid < 8) g_rh[(gbase >> 1) + tid] = __floats2half2_rn(sV[2 * tid], sV[2 * tid + 1]);
    bt += G;
    grid_barrier(bt);                // leading syncthreads orders the publish

    // ---- Phase B: stage r*h, cand = tanh(Wh u + Ph), update ----
    ((uint2*)sh)[tid] = ldcv2((const uint2*)g_rh + tid);
    __syncthreads();
    {
      const uint4* hp = (const uint4*)(shv + lane * 16);
#pragma unroll
      for (int q = 0; q < 4; q++) hb[q] = hp[q];
    }

    // weight fragments from SMEM (contiguous, LDS.128)
    uint4 wb0[4], wb1[4];
    {
      const uint4* p0 = (const uint4*)(wh0 + lane * 16);
      const uint4* p1 = (const uint4*)(wh1 + lane * 16);
#pragma unroll
      for (int q = 0; q < 4; q++) { wb0[q] = p0[q]; wb1[q] = p1[q]; }
    }
    float ah0 = dot16h((const __half2*)wb0, hh);
    float ah1 = dot16h((const __half2*)wb1, hh);
#pragma unroll
    for (int o = 16; o; o >>= 1) {
      ah0 += __shfl_xor_sync(0xffffffffu, ah0, o);
      ah1 += __shfl_xor_sync(0xffffffffu, ah1, o);
    }
    if (lane == 0) {
      sRed[chunk][pr]     = ah0;
      sRed[chunk][pr + 1] = ah1;
    }
    __syncthreads();

    if (tid < 16) {
      float val = sRed[0][tid] + sRed[1][tid] + ph_cur;
      float e = __expf(2.0f * val);
      float cand = 1.0f - __fdividef(2.0f, e + 1.0f);   // tanh
      float z = sz[tid];
      float hold = sHold[tid];
      float hn = fmaf(z, cand - hold, hold);
      out[(size_t)t * HID + gbase + tid] = hn;          // fp32-exact output
      sHown[tid] = hn;                                  // fp32 state carry
      sV[tid] = hn;
      if (t == SEQ - 1) out[(size_t)SEQ * HID + gbase + tid] = hn;
    }
    __syncthreads();
    if (tid < 8) g_h[(gbase >> 1) + tid] = __floats2half2_rn(sV[2 * tid], sV[2 * tid + 1]);
    bt += G;
    grid_barrier(bt);

    pzr_cur = pzr_nxt;
    ph_cur  = ph_nxt;
  }
}

// ---------------- launch ----------------
extern "C" void kernel_launch(void* const* d_in, const int* in_sizes, int n_in,
                              void* d_out, int out_size) {
  const float* X  = (const float*)d_in[0];
  const float* Wz = (const float*)d_in[1];
  const float* Wr = (const float*)d_in[2];
  const float* Wh = (const float*)d_in[3];
  const float* bz = (const float*)d_in[4];
  const float* br = (const float*)d_in[5];
  const float* bh = (const float*)d_in[6];
  float* out = (float*)d_out;

  init_kernel<<<8, 256>>>();

  {
    size_t total4 = (size_t)SEQ * EMB / 4;
    convert_X_kernel<<<(int)((total4 + 255) / 256), 256>>>(X);
  }
  {
    size_t total4 = 3ull * HID * WROW / 4;
    convert_W_kernel<<<(int)((total4 + 255) / 256), 256>>>(Wz, Wr, Wh);
  }
  {
    dim3 grid(HID / 128, SEQ / 128, 3);
    xproj_mma_kernel<<<grid, 256>>>(bz, br, bh);
  }

  cudaFuncSetAttribute(gru_kernel, cudaFuncAttributeMaxDynamicSharedMemorySize, GRU_SMEM);
  gru_kernel<<<G, RT, GRU_SMEM>>>(out);
}

// round 15
// speedup vs baseline: 1.0438x; 1.0438x over previous
#include <cuda_runtime.h>
#include <cuda_fp16.h>
#include <cstdint>
#include <math.h>

#define SEQ 8192
#define EMB 2048
#define HID 2048
#define WROW (EMB + HID)

// ---------------- persistent recurrent kernel config ----------------
#define G   128   // CTAs (<= 148 SMs, 1 CTA/SM -> all co-resident)
#define RPC 16    // rows per CTA (HID / G)
#define RT  512   // threads per CTA

// ---------------- device scratch ----------------
__device__ __align__(16) __half2 g_wh[3ull * HID * HID / 2];   // fp16 h-part weights [m][row][col]
__device__ __align__(16) __half2 g_wx[3ull * HID * EMB / 2];   // fp16 x-part weights [m][row][col]
__device__ __align__(16) __half2 g_Xh[(size_t)SEQ * EMB / 2];  // fp16 inputs
__device__ float    g_P [3ull * SEQ * HID];   // precomputed x-projections + bias
__device__ __align__(16) __half2 g_h [HID / 2];   // hidden state exchange (fp16, 4KB)
__device__ __align__(16) __half2 g_rh[HID / 2];   // r*h exchange (fp16, 4KB)
__device__ unsigned g_count;

// ---------------- init (reset per launch / per graph replay) ----------------
__global__ void init_kernel() {
  int i = blockIdx.x * blockDim.x + threadIdx.x;
  if (i < HID / 2) ((unsigned*)g_h)[i] = 0u;
  if (i == 0) g_count = 0u;
}

// ---------------- fp32 -> fp16 conversions ----------------
__global__ void convert_X_kernel(const float* __restrict__ X) {
  size_t i4 = (size_t)blockIdx.x * blockDim.x + threadIdx.x;
  if (i4 >= (size_t)SEQ * EMB / 4) return;
  float4 v = ((const float4*)X)[i4];
  g_Xh[i4 * 2 + 0] = __floats2half2_rn(v.x, v.y);
  g_Xh[i4 * 2 + 1] = __floats2half2_rn(v.z, v.w);
}

__global__ void convert_W_kernel(const float* __restrict__ Wz,
                                 const float* __restrict__ Wr,
                                 const float* __restrict__ Wh) {
  size_t i4 = (size_t)blockIdx.x * blockDim.x + threadIdx.x;
  const size_t total4 = 3ull * HID * WROW / 4;
  if (i4 >= total4) return;
  size_t idx = i4 * 4;
  int m = (int)(idx / ((size_t)HID * WROW));
  size_t rem = idx - (size_t)m * HID * WROW;
  int r = (int)(rem / WROW);
  int c = (int)(rem - (size_t)r * WROW);
  const float* W = (m == 0) ? Wz : ((m == 1) ? Wr : Wh);
  float4 v = ((const float4*)(W + (size_t)r * WROW + c))[0];
  __half2 h01 = __floats2half2_rn(v.x, v.y);
  __half2 h23 = __floats2half2_rn(v.z, v.w);
  if (c < EMB) {
    size_t o = ((size_t)(m * HID + r) * EMB + c) / 2;
    g_wx[o] = h01;
    g_wx[o + 1] = h23;
  } else {
    size_t o = ((size_t)(m * HID + r) * HID + (c - EMB)) / 2;
    g_wh[o] = h01;
    g_wh[o + 1] = h23;
  }
}

// ---------------- tensor-core x-projection GEMM ----------------
__device__ __forceinline__ uint32_t smem_u32(const void* p) {
  return (uint32_t)__cvta_generic_to_shared(p);
}

__device__ __forceinline__ void ldsm4(uint32_t* r, uint32_t addr) {
  asm volatile("ldmatrix.sync.aligned.m8n8.x4.shared.b16 {%0,%1,%2,%3}, [%4];"
    : "=r"(r[0]), "=r"(r[1]), "=r"(r[2]), "=r"(r[3]) : "r"(addr));
}

__device__ __forceinline__ void mma16816(float* d, const uint32_t* a, const uint32_t* b) {
  asm volatile(
    "mma.sync.aligned.m16n8k16.row.col.f32.f16.f16.f32 "
    "{%0,%1,%2,%3}, {%4,%5,%6,%7}, {%8,%9}, {%0,%1,%2,%3};"
    : "+f"(d[0]), "+f"(d[1]), "+f"(d[2]), "+f"(d[3])
    : "r"(a[0]), "r"(a[1]), "r"(a[2]), "r"(a[3]), "r"(b[0]), "r"(b[1]));
}

__global__ __launch_bounds__(256) void xproj_mma_kernel(
    const float* __restrict__ bz, const float* __restrict__ br, const float* __restrict__ bh) {
  __shared__ __half As[128][40];
  __shared__ __half Bs[128][40];

  int m  = blockIdx.z;
  int bM = blockIdx.y * 128;
  int bN = blockIdx.x * 128;
  const __half* Asrc = (const __half*)g_Xh;
  const __half* Bsrc = (const __half*)g_wx + (size_t)m * HID * EMB;
  const float* bias = (m == 0) ? bz : ((m == 1) ? br : bh);

  int tid = threadIdx.x;
  int lane = tid & 31;
  int wid = tid >> 5;
  int wm = wid >> 1;
  int wn = wid & 1;

  float d[2][8][4];
#pragma unroll
  for (int mf = 0; mf < 2; mf++)
#pragma unroll
    for (int nf = 0; nf < 8; nf++)
#pragma unroll
      for (int q = 0; q < 4; q++) d[mf][nf][q] = 0.0f;

  for (int kt = 0; kt < EMB; kt += 32) {
#pragma unroll
    for (int i = 0; i < 2; i++) {
      int f = tid + i * 256;
      int row = f >> 2;
      int q = f & 3;
      *(uint4*)&As[row][q * 8] = *(const uint4*)&Asrc[(size_t)(bM + row) * EMB + kt + q * 8];
      *(uint4*)&Bs[row][q * 8] = *(const uint4*)&Bsrc[(size_t)(bN + row) * EMB + kt + q * 8];
    }
    __syncthreads();

#pragma unroll
    for (int ks = 0; ks < 32; ks += 16) {
      uint32_t a[2][4];
#pragma unroll
      for (int mf = 0; mf < 2; mf++) {
        int r = wm * 32 + mf * 16 + (lane & 15);
        int c = ks + ((lane >> 4) << 3);
        ldsm4(a[mf], smem_u32(&As[r][c]));
      }
      uint32_t b[8][2];
#pragma unroll
      for (int nf2 = 0; nf2 < 4; nf2++) {
        int t4 = lane >> 3;
        int r = wn * 64 + nf2 * 16 + ((t4 >> 1) << 3) + (lane & 7);
        int c = ks + ((t4 & 1) << 3);
        uint32_t rr[4];
        ldsm4(rr, smem_u32(&Bs[r][c]));
        b[nf2 * 2][0]     = rr[0];
        b[nf2 * 2][1]     = rr[1];
        b[nf2 * 2 + 1][0] = rr[2];
        b[nf2 * 2 + 1][1] = rr[3];
      }
#pragma unroll
      for (int mf = 0; mf < 2; mf++)
#pragma unroll
        for (int nf = 0; nf < 8; nf++) mma16816(d[mf][nf], a[mf], b[nf]);
    }
    __syncthreads();
  }

  int rowg = lane >> 2;
  int colg = (lane & 3) * 2;
#pragma unroll
  for (int mf = 0; mf < 2; mf++) {
#pragma unroll
    for (int nf = 0; nf < 8; nf++) {
      int t0 = bM + wm * 32 + mf * 16 + rowg;
      int c0 = bN + wn * 64 + nf * 8 + colg;
      float b0 = bias[c0];
      float b1 = bias[c0 + 1];
      float2 v0;
      v0.x = d[mf][nf][0] + b0;
      v0.y = d[mf][nf][1] + b1;
      float2 v1;
      v1.x = d[mf][nf][2] + b0;
      v1.y = d[mf][nf][3] + b1;
      *(float2*)&g_P[((size_t)m * SEQ + t0    ) * HID + c0] = v0;
      *(float2*)&g_P[((size_t)m * SEQ + t0 + 8) * HID + c0] = v1;
    }
  }
}

// ---------------- grid barrier pieces (R7's measured-best protocol) ----------------
__device__ __forceinline__ void barrier_arrive() {
  asm volatile("red.release.gpu.global.add.u32 [%0], %1;" :: "l"(&g_count), "r"(1u) : "memory");
}
__device__ __forceinline__ void barrier_wait(unsigned target) {
  unsigned v;
  asm volatile("ld.acquire.gpu.u32 %0, [%1];" : "=r"(v) : "l"(&g_count) : "memory");
  while (v < target) {
    __nanosleep(32);
    asm volatile("ld.acquire.gpu.u32 %0, [%1];" : "=r"(v) : "l"(&g_count) : "memory");
  }
}
// Combined (R7 verbatim shape) for phase B
__device__ __forceinline__ void grid_barrier(unsigned target) {
  __syncthreads();
  if (threadIdx.x == 0) {
    barrier_arrive();
    barrier_wait(target);
  }
  __syncthreads();
}

// L1-bypass 8B load (exchange buffers mutate cross-SM every step)
__device__ __forceinline__ uint2 ldcv2(const uint2* p) {
  uint2 v;
  asm volatile("ld.global.cv.v2.u32 {%0,%1}, [%2];" : "=r"(v.x), "=r"(v.y) : "l"(p));
  return v;
}

// ---------------- persistent GRU recurrence ----------------
// SMEM: fp16 Wh [RPC][HID] (64KB) + float h vector (8KB). fp32 compute (R7 math).
#define GRU_SMEM (RPC * HID * 2 + HID * 4)

__global__ __launch_bounds__(RT, 1) void gru_kernel(float* __restrict__ out) {
  extern __shared__ char smem_raw[];
  __half2* sWh = (__half2*)smem_raw;                       // [RPC][1024] half2
  float*   sh  = (float*)(smem_raw + RPC * HID * sizeof(__half));
  __shared__ float sRed[2][32];
  __shared__ float sz[RPC];
  __shared__ float sHold[RPC];

  const int b = blockIdx.x;
  const int tid = threadIdx.x;
  const int lane = tid & 31;
  const int w = tid >> 5;           // 16 warps
  const int chunk = w >> 3;         // vector half: 0 / 1
  const int pr = (w & 7) * 2;       // local row pair
  const int gbase = b * RPC;

  // Load Wh rows (m=2) into SMEM once.
  {
    const uint4* gsrc = (const uint4*)(g_wh + (2ull * HID * HID + (size_t)gbase * HID) / 2);
    uint4* sdst = (uint4*)smem_raw;
    for (int it = tid; it < RPC * HID / 8; it += RT) sdst[it] = gsrc[it];
  }

  // Preload z,r weight rows into registers (R7 mapping: o = (chunk<<9)+(j<<5)+lane).
  __half2 rz0[16], rz1[16], rr0[16], rr1[16];
  {
    const __half2* z0 = g_wh + (size_t)(0 * HID + gbase + pr    ) * (HID / 2);
    const __half2* z1 = g_wh + (size_t)(0 * HID + gbase + pr + 1) * (HID / 2);
    const __half2* r0 = g_wh + (size_t)(1 * HID + gbase + pr    ) * (HID / 2);
    const __half2* r1 = g_wh + (size_t)(1 * HID + gbase + pr + 1) * (HID / 2);
#pragma unroll
    for (int j = 0; j < 16; j++) {
      int o = (chunk << 9) + (j << 5) + lane;
      rz0[j] = z0[o];
      rz1[j] = z1[o];
      rr0[j] = r0[o];
      rr1[j] = r1[o];
    }
  }
  __syncthreads();

  const float2*  shv = (const float2*)sh + (chunk << 9);
  const __half2* wh0 = sWh + (pr    ) * (HID / 2) + (chunk << 9);
  const __half2* wh1 = sWh + (pr + 1) * (HID / 2) + (chunk << 9);

  unsigned bt = 0;

  // Software-pipelined P prefetch (step t's values loaded during step t-1).
  float pzr_cur = 0.0f, ph_cur = 0.0f;
  if (tid < 32) {
    int row = tid & 15;
    int mm  = tid >> 4;
    pzr_cur = g_P[((size_t)mm * SEQ + 0) * HID + gbase + row];
  }
  if (tid < 16) ph_cur = g_P[((size_t)2 * SEQ + 0) * HID + gbase + tid];

  for (int t = 0; t < SEQ; t++) {
    int tn = (t + 1 < SEQ) ? (t + 1) : (SEQ - 1);
    float pzr_nxt = 0.0f, ph_nxt = 0.0f;
    if (tid < 32) {
      int row = tid & 15;
      int mm  = tid >> 4;
      pzr_nxt = g_P[((size_t)mm * SEQ + tn) * HID + gbase + row];
    }
    if (tid < 16) ph_nxt = g_P[((size_t)2 * SEQ + tn) * HID + gbase + tid];

    // ---- Phase A: stage h (half2 global -> float SMEM) ----
    {
      uint2 hv = ldcv2((const uint2*)g_h + tid);
      __half2* hp = (__half2*)&hv;
      float2 f0 = __half22float2(hp[0]);
      float2 f1 = __half22float2(hp[1]);
      float4 f;
      f.x = f0.x; f.y = f0.y; f.z = f1.x; f.w = f1.y;
      ((float4*)sh)[tid] = f;
    }
    __syncthreads();

    // ---- r dots only (publish early; z overlapped with arrival spread) ----
    float ar0 = 0.f, ar1 = 0.f;
#pragma unroll
    for (int j = 0; j < 16; j++) {
      float2 h2 = shv[(j << 5) + lane];
      float2 c0 = __half22float2(rr0[j]);
      float2 c1 = __half22float2(rr1[j]);
      ar0 = fmaf(c0.x, h2.x, fmaf(c0.y, h2.y, ar0));
      ar1 = fmaf(c1.x, h2.x, fmaf(c1.y, h2.y, ar1));
    }
#pragma unroll
    for (int o = 16; o; o >>= 1) {
      ar0 += __shfl_xor_sync(0xffffffffu, ar0, o);
      ar1 += __shfl_xor_sync(0xffffffffu, ar1, o);
    }
    if (lane == 0) {
      sRed[chunk][16 + pr]     = ar0;
      sRed[chunk][16 + pr + 1] = ar1;
    }
    __syncthreads();

    // Publish r*h as half2 (warp 0 fully converged -> full-mask shfl pack is safe).
    if (tid < 32) {
      float rhv = 0.0f;
      if (tid >= 16) {
        int row = tid - 16;
        float val = sRed[0][tid] + sRed[1][tid] + pzr_cur;
        float sg = 1.0f / (1.0f + __expf(-val));
        rhv = sg * sh[gbase + row];
      }
      float other = __shfl_xor_sync(0xffffffffu, rhv, 1);
      if (tid >= 16 && !(tid & 1)) {
        int row = tid - 16;
        g_rh[(gbase + row) >> 1] = __floats2half2_rn(rhv, other);
      }
    }
    __syncthreads();                  // order publish before release-arrival
    if (tid == 0) barrier_arrive();
    bt += G;

    // ---- z dots while other CTAs arrive ----
    float az0 = 0.f, az1 = 0.f;
#pragma unroll
    for (int j = 0; j < 16; j++) {
      float2 h2 = shv[(j << 5) + lane];
      float2 a0 = __half22float2(rz0[j]);
      float2 a1 = __half22float2(rz1[j]);
      az0 = fmaf(a0.x, h2.x, fmaf(a0.y, h2.y, az0));
      az1 = fmaf(a1.x, h2.x, fmaf(a1.y, h2.y, az1));
    }
#pragma unroll
    for (int o = 16; o; o >>= 1) {
      az0 += __shfl_xor_sync(0xffffffffu, az0, o);
      az1 += __shfl_xor_sync(0xffffffffu, az1, o);
    }
    if (lane == 0) {
      sRed[chunk][pr]     = az0;
      sRed[chunk][pr + 1] = az1;
    }
    __syncthreads();

    if (tid < 16) {
      float val = sRed[0][tid] + sRed[1][tid] + pzr_cur;
      sz[tid]    = 1.0f / (1.0f + __expf(-val));
      sHold[tid] = sh[gbase + tid];
    }
    if (tid == 0) barrier_wait(bt);
    __syncthreads();

    // ---- Phase B: stage r*h, cand = tanh(Wh u + Ph), update ----
    {
      uint2 hv = ldcv2((const uint2*)g_rh + tid);
      __half2* hp = (__half2*)&hv;
      float2 f0 = __half22float2(hp[0]);
      float2 f1 = __half22float2(hp[1]);
      float4 f;
      f.x = f0.x; f.y = f0.y; f.z = f1.x; f.w = f1.y;
      ((float4*)sh)[tid] = f;
    }
    __syncthreads();

    float ah0 = 0.f, ah1 = 0.f;
#pragma unroll
    for (int j = 0; j < 16; j++) {
      int o = (j << 5) + lane;
      float2 h2 = shv[o];
      float2 a0 = __half22float2(wh0[o]);
      float2 a1 = __half22float2(wh1[o]);
      ah0 = fmaf(a0.x, h2.x, fmaf(a0.y, h2.y, ah0));
      ah1 = fmaf(a1.x, h2.x, fmaf(a1.y, h2.y, ah1));
    }
#pragma unroll
    for (int o = 16; o; o >>= 1) {
      ah0 += __shfl_xor_sync(0xffffffffu, ah0, o);
      ah1 += __shfl_xor_sync(0xffffffffu, ah1, o);
    }
    if (lane == 0) {
      sRed[chunk][pr]     = ah0;
      sRed[chunk][pr + 1] = ah1;
    }
    __syncthreads();

    if (tid < 32) {
      float hn = 0.0f;
      if (tid < 16) {
        float val = sRed[0][tid] + sRed[1][tid] + ph_cur;
        float e = __expf(2.0f * val);
        float cand = 1.0f - __fdividef(2.0f, e + 1.0f);   // tanh
        float z = sz[tid];
        float hold = sHold[tid];
        hn = fmaf(z, cand - hold, hold);
        out[(size_t)t * HID + gbase + tid] = hn;          // fp32-exact output
        if (t == SEQ - 1) out[(size_t)SEQ * HID + gbase + tid] = hn;
      }
      float other = __shfl_xor_sync(0xffffffffu, hn, 1);
      if (tid < 16 && !(tid & 1))
        g_h[(gbase + tid) >> 1] = __floats2half2_rn(hn, other);
    }
    bt += G;
    grid_barrier(bt);                 // leading syncthreads orders h publish

    pzr_cur = pzr_nxt;
    ph_cur  = ph_nxt;
  }
}

// ---------------- launch ----------------
extern "C" void kernel_launch(void* const* d_in, const int* in_sizes, int n_in,
                              void* d_out, int out_size) {
  const float* X  = (const float*)d_in[0];
  const float* Wz = (const float*)d_in[1];
  const float* Wr = (const float*)d_in[2];
  const float* Wh = (const float*)d_in[3];
  const float* bz = (const float*)d_in[4];
  const float* br = (const float*)d_in[5];
  const float* bh = (const float*)d_in[6];
  float* out = (float*)d_out;

  init_kernel<<<8, 256>>>();

  {
    size_t total4 = (size_t)SEQ * EMB / 4;
    convert_X_kernel<<<(int)((total4 + 255) / 256), 256>>>(X);
  }
  {
    size_t total4 = 3ull * HID * WROW / 4;
    convert_W_kernel<<<(int)((total4 + 255) / 256), 256>>>(Wz, Wr, Wh);
  }
  {
    dim3 grid(HID / 128, SEQ / 128, 3);
    xproj_mma_kernel<<<grid, 256>>>(bz, br, bh);
  }

  cudaFuncSetAttribute(gru_kernel, cudaFuncAttributeMaxDynamicSharedMemorySize, GRU_SMEM);
  gru_kernel<<<G, RT, GRU_SMEM>>>(out);
}